// round 12
// baseline (speedup 1.0000x reference)
#include <cuda_runtime.h>
#include <math.h>

// GeodesicLoss: reference initializes velocity to zero, so the geodesic ODE
// acc = -Gamma v v is identically zero for all 10 steps -> traj == outputs.
// Result is exactly mean_b || outputs_b - targets_b ||_2.
// Pure streaming reduction over 128 MiB -> DRAM-bound.
//
// R12: exact R3 structure (best measured: 25.1us; 4096x256, 8 front-batched
// LDG.128, fused last-block-done tail) with ONE change: loads carry the
// L2::256B promotion hint (ld.global.nc.L2::256B.v4.f32) to fetch DRAM in
// 256B granules and lift the stream from 67.5% toward 72% of HBM.

#define B_ROWS   524288
#define D_DIM    32
#define THREADS  256
#define NBLOCKS  4096
#define ROWS_PER_ITER (THREADS / 8)                         // 32 rows / block-iter
#define ITERS 4                                             // 128 rows / block
#define F4_PER_ITER (ROWS_PER_ITER * (D_DIM / 4))           // 256 float4 stride

__device__ float        g_partials[NBLOCKS];
__device__ unsigned int g_done_count = 0;

__device__ __forceinline__ float4 ldg_nc_256(const float4* p) {
    float4 v;
    asm volatile("ld.global.nc.L2::256B.v4.f32 {%0,%1,%2,%3}, [%4];"
                 : "=f"(v.x), "=f"(v.y), "=f"(v.z), "=f"(v.w)
                 : "l"(p));
    return v;
}

__global__ __launch_bounds__(THREADS)
void geodesic_loss_fused_kernel(const float* __restrict__ outputs,
                                const float* __restrict__ targets,
                                float* __restrict__ out) {
    const int sub      = threadIdx.x & 7;          // which float4 of the row
    const int row_in_b = threadIdx.x >> 3;         // row slot within block-iter
    const int base_row = blockIdx.x * (ROWS_PER_ITER * ITERS);

    const float4* __restrict__ o4 = reinterpret_cast<const float4*>(outputs);
    const float4* __restrict__ t4 = reinterpret_cast<const float4*>(targets);

    const int idx0 = (base_row + row_in_b) * (D_DIM / 4) + sub;

    // ---- front-batched loads: 8 independent LDG.128 in flight ----
    float4 a0 = ldg_nc_256(&o4[idx0 + 0 * F4_PER_ITER]);
    float4 a1 = ldg_nc_256(&o4[idx0 + 1 * F4_PER_ITER]);
    float4 a2 = ldg_nc_256(&o4[idx0 + 2 * F4_PER_ITER]);
    float4 a3 = ldg_nc_256(&o4[idx0 + 3 * F4_PER_ITER]);
    float4 b0 = ldg_nc_256(&t4[idx0 + 0 * F4_PER_ITER]);
    float4 b1 = ldg_nc_256(&t4[idx0 + 1 * F4_PER_ITER]);
    float4 b2 = ldg_nc_256(&t4[idx0 + 2 * F4_PER_ITER]);
    float4 b3 = ldg_nc_256(&t4[idx0 + 3 * F4_PER_ITER]);

    float dx, dy, dz, dw;
    #define SSQ(a, b) (dx = a.x - b.x, dy = a.y - b.y, dz = a.z - b.z, \
                       dw = a.w - b.w, dx*dx + dy*dy + dz*dz + dw*dw)
    float s0 = SSQ(a0, b0);
    float s1 = SSQ(a1, b1);
    float s2 = SSQ(a2, b2);
    float s3 = SSQ(a3, b3);
    #undef SSQ

    // Reduce the 8 lanes covering each row (4 independent chains)
    s0 += __shfl_xor_sync(0xFFFFFFFFu, s0, 1);
    s1 += __shfl_xor_sync(0xFFFFFFFFu, s1, 1);
    s2 += __shfl_xor_sync(0xFFFFFFFFu, s2, 1);
    s3 += __shfl_xor_sync(0xFFFFFFFFu, s3, 1);
    s0 += __shfl_xor_sync(0xFFFFFFFFu, s0, 2);
    s1 += __shfl_xor_sync(0xFFFFFFFFu, s1, 2);
    s2 += __shfl_xor_sync(0xFFFFFFFFu, s2, 2);
    s3 += __shfl_xor_sync(0xFFFFFFFFu, s3, 2);
    s0 += __shfl_xor_sync(0xFFFFFFFFu, s0, 4);
    s1 += __shfl_xor_sync(0xFFFFFFFFu, s1, 4);
    s2 += __shfl_xor_sync(0xFFFFFFFFu, s2, 4);
    s3 += __shfl_xor_sync(0xFFFFFFFFu, s3, 4);

    float acc = 0.0f;
    if (sub == 0)
        acc = sqrtf(s0) + sqrtf(s1) + sqrtf(s2) + sqrtf(s3);

    // Combine the 4 row-accumulators per warp (lanes 0,8,16,24 nonzero)
    acc += __shfl_xor_sync(0xFFFFFFFFu, acc, 8);
    acc += __shfl_xor_sync(0xFFFFFFFFu, acc, 16);

    __shared__ float wsum[THREADS / 32];
    if ((threadIdx.x & 31) == 0)
        wsum[threadIdx.x >> 5] = acc;
    __syncthreads();

    __shared__ bool s_is_last;
    if (threadIdx.x == 0) {
        float bsum = 0.0f;
        #pragma unroll
        for (int i = 0; i < THREADS / 32; i++)
            bsum += wsum[i];
        g_partials[blockIdx.x] = bsum;
        __threadfence();
        unsigned int prev = atomicAdd(&g_done_count, 1u);
        s_is_last = (prev == NBLOCKS - 1);
    }
    __syncthreads();

    if (s_is_last) {
        // Final reduce over NBLOCKS partials via float4, fixed order.
        const float4* __restrict__ p4 =
            reinterpret_cast<const float4*>(g_partials);
        float s = 0.0f;
        #pragma unroll
        for (int i = threadIdx.x; i < NBLOCKS / 4; i += THREADS) {
            float4 v = p4[i];
            s += (v.x + v.y) + (v.z + v.w);
        }

        s += __shfl_xor_sync(0xFFFFFFFFu, s, 1);
        s += __shfl_xor_sync(0xFFFFFFFFu, s, 2);
        s += __shfl_xor_sync(0xFFFFFFFFu, s, 4);
        s += __shfl_xor_sync(0xFFFFFFFFu, s, 8);
        s += __shfl_xor_sync(0xFFFFFFFFu, s, 16);

        __shared__ float fsum[THREADS / 32];
        if ((threadIdx.x & 31) == 0)
            fsum[threadIdx.x >> 5] = s;
        __syncthreads();

        if (threadIdx.x == 0) {
            float tot = 0.0f;
            #pragma unroll
            for (int i = 0; i < THREADS / 32; i++)
                tot += fsum[i];
            out[0] = tot * (1.0f / (float)B_ROWS);
            g_done_count = 0;   // reset for next graph replay
        }
    }
}

extern "C" void kernel_launch(void* const* d_in, const int* in_sizes, int n_in,
                              void* d_out, int out_size) {
    const float* outputs = (const float*)d_in[0];
    const float* targets = (const float*)d_in[1];
    // d_in[2] (christoffel_symbols) is mathematically dead: vel starts at 0.
    float* out = (float*)d_out;

    geodesic_loss_fused_kernel<<<NBLOCKS, THREADS>>>(outputs, targets, out);
}

// round 13
// speedup vs baseline: 1.0922x; 1.0922x over previous
#include <cuda_runtime.h>
#include <math.h>

// GeodesicLoss: reference initializes velocity to zero, so the geodesic ODE
// acc = -Gamma v v is identically zero for all 10 steps -> traj == outputs.
// Result is exactly mean_b || outputs_b - targets_b ||_2.
// Pure streaming reduction over 128 MiB -> DRAM-bound.
//
// R13: R3's champion stream (25.1us: 4096x256, 8 front-batched LDG.128,
// plain loads) with a cheaper tail: blocks signal completion with a
// fire-and-forget red.release (no returning atomicAdd to wait on -> blocks
// retire immediately); block 0 spin-waits on the counter with acquire loads
// and performs the fixed-order final reduce. Deterministic; counter
// self-resets for graph replay.

#define B_ROWS   524288
#define D_DIM    32
#define THREADS  256
#define NBLOCKS  4096
#define ROWS_PER_ITER (THREADS / 8)                         // 32 rows / block-iter
#define ITERS 4                                             // 128 rows / block
#define F4_PER_ITER (ROWS_PER_ITER * (D_DIM / 4))           // 256 float4 stride

__device__ float        g_partials[NBLOCKS];
__device__ unsigned int g_done_count = 0;

__global__ __launch_bounds__(THREADS)
void geodesic_loss_fused_kernel(const float* __restrict__ outputs,
                                const float* __restrict__ targets,
                                float* __restrict__ out) {
    const int sub      = threadIdx.x & 7;          // which float4 of the row
    const int row_in_b = threadIdx.x >> 3;         // row slot within block-iter
    const int base_row = blockIdx.x * (ROWS_PER_ITER * ITERS);

    const float4* __restrict__ o4 = reinterpret_cast<const float4*>(outputs);
    const float4* __restrict__ t4 = reinterpret_cast<const float4*>(targets);

    const int idx0 = (base_row + row_in_b) * (D_DIM / 4) + sub;

    // ---- front-batched loads: 8 independent LDG.128 in flight ----
    float4 a0 = o4[idx0 + 0 * F4_PER_ITER];
    float4 a1 = o4[idx0 + 1 * F4_PER_ITER];
    float4 a2 = o4[idx0 + 2 * F4_PER_ITER];
    float4 a3 = o4[idx0 + 3 * F4_PER_ITER];
    float4 b0 = t4[idx0 + 0 * F4_PER_ITER];
    float4 b1 = t4[idx0 + 1 * F4_PER_ITER];
    float4 b2 = t4[idx0 + 2 * F4_PER_ITER];
    float4 b3 = t4[idx0 + 3 * F4_PER_ITER];

    float dx, dy, dz, dw;
    #define SSQ(a, b) (dx = a.x - b.x, dy = a.y - b.y, dz = a.z - b.z, \
                       dw = a.w - b.w, dx*dx + dy*dy + dz*dz + dw*dw)
    float s0 = SSQ(a0, b0);
    float s1 = SSQ(a1, b1);
    float s2 = SSQ(a2, b2);
    float s3 = SSQ(a3, b3);
    #undef SSQ

    // Reduce the 8 lanes covering each row (4 independent chains)
    s0 += __shfl_xor_sync(0xFFFFFFFFu, s0, 1);
    s1 += __shfl_xor_sync(0xFFFFFFFFu, s1, 1);
    s2 += __shfl_xor_sync(0xFFFFFFFFu, s2, 1);
    s3 += __shfl_xor_sync(0xFFFFFFFFu, s3, 1);
    s0 += __shfl_xor_sync(0xFFFFFFFFu, s0, 2);
    s1 += __shfl_xor_sync(0xFFFFFFFFu, s1, 2);
    s2 += __shfl_xor_sync(0xFFFFFFFFu, s2, 2);
    s3 += __shfl_xor_sync(0xFFFFFFFFu, s3, 2);
    s0 += __shfl_xor_sync(0xFFFFFFFFu, s0, 4);
    s1 += __shfl_xor_sync(0xFFFFFFFFu, s1, 4);
    s2 += __shfl_xor_sync(0xFFFFFFFFu, s2, 4);
    s3 += __shfl_xor_sync(0xFFFFFFFFu, s3, 4);

    float acc = 0.0f;
    if (sub == 0)
        acc = sqrtf(s0) + sqrtf(s1) + sqrtf(s2) + sqrtf(s3);

    // Combine the 4 row-accumulators per warp (lanes 0,8,16,24 nonzero)
    acc += __shfl_xor_sync(0xFFFFFFFFu, acc, 8);
    acc += __shfl_xor_sync(0xFFFFFFFFu, acc, 16);

    __shared__ float wsum[THREADS / 32];
    if ((threadIdx.x & 31) == 0)
        wsum[threadIdx.x >> 5] = acc;
    __syncthreads();

    if (threadIdx.x == 0) {
        float bsum = 0.0f;
        #pragma unroll
        for (int i = 0; i < THREADS / 32; i++)
            bsum += wsum[i];
        g_partials[blockIdx.x] = bsum;
        // Fire-and-forget release increment: orders the partial store,
        // returns nothing -> the block never waits on the LTS atomic queue.
        asm volatile("red.release.gpu.global.add.u32 [%0], 1;"
                     :: "l"(&g_done_count) : "memory");
    }

    // Designated winner: block 0 spin-waits for all partials, then reduces.
    if (blockIdx.x == 0) {
        __shared__ bool s_ready;
        if (threadIdx.x == 0) {
            unsigned int c;
            do {
                __nanosleep(256);
                asm volatile("ld.acquire.gpu.global.u32 %0, [%1];"
                             : "=r"(c) : "l"(&g_done_count));
            } while (c < NBLOCKS);
            s_ready = true;
        }
        __syncthreads();
        (void)s_ready;

        // Final reduce over NBLOCKS partials via float4, fixed order.
        const float4* __restrict__ p4 =
            reinterpret_cast<const float4*>(g_partials);
        float s = 0.0f;
        #pragma unroll
        for (int i = threadIdx.x; i < NBLOCKS / 4; i += THREADS) {
            float4 v = __ldcg(&p4[i]);
            s += (v.x + v.y) + (v.z + v.w);
        }

        s += __shfl_xor_sync(0xFFFFFFFFu, s, 1);
        s += __shfl_xor_sync(0xFFFFFFFFu, s, 2);
        s += __shfl_xor_sync(0xFFFFFFFFu, s, 4);
        s += __shfl_xor_sync(0xFFFFFFFFu, s, 8);
        s += __shfl_xor_sync(0xFFFFFFFFu, s, 16);

        __shared__ float fsum[THREADS / 32];
        if ((threadIdx.x & 31) == 0)
            fsum[threadIdx.x >> 5] = s;
        __syncthreads();

        if (threadIdx.x == 0) {
            float tot = 0.0f;
            #pragma unroll
            for (int i = 0; i < THREADS / 32; i++)
                tot += fsum[i];
            out[0] = tot * (1.0f / (float)B_ROWS);
            g_done_count = 0;   // reset for next graph replay
        }
    }
}

extern "C" void kernel_launch(void* const* d_in, const int* in_sizes, int n_in,
                              void* d_out, int out_size) {
    const float* outputs = (const float*)d_in[0];
    const float* targets = (const float*)d_in[1];
    // d_in[2] (christoffel_symbols) is mathematically dead: vel starts at 0.
    float* out = (float*)d_out;

    geodesic_loss_fused_kernel<<<NBLOCKS, THREADS>>>(outputs, targets, out);
}

// round 14
// speedup vs baseline: 1.1122x; 1.0183x over previous
#include <cuda_runtime.h>
#include <math.h>

// GeodesicLoss: reference initializes velocity to zero, so the geodesic ODE
// acc = -Gamma v v is identically zero for all 10 steps -> traj == outputs.
// Result is exactly mean_b || outputs_b - targets_b ||_2.
// Pure streaming reduction over 128 MiB -> DRAM-bound.
//
// R14: byte-identical to R3 (champion, 25.1us) EXCEPT __launch_bounds__(256,4)
// raises the per-thread register budget to 64 so ptxas can keep all 8
// front-batched LDG.128 results live (R3 was pinned at regs=32 -> loads
// chained in pairs, MLP ~2-3). True per-thread MLP=8 should lift the stream
// from 67% toward 72% DRAM.

#define B_ROWS   524288
#define D_DIM    32
#define THREADS  256
#define NBLOCKS  4096
#define ROWS_PER_ITER (THREADS / 8)                         // 32 rows / block-iter
#define ITERS 4                                             // 128 rows / block
#define F4_PER_ITER (ROWS_PER_ITER * (D_DIM / 4))           // 256 float4 stride

__device__ float        g_partials[NBLOCKS];
__device__ unsigned int g_done_count = 0;

__global__ __launch_bounds__(THREADS, 4)
void geodesic_loss_fused_kernel(const float* __restrict__ outputs,
                                const float* __restrict__ targets,
                                float* __restrict__ out) {
    const int sub      = threadIdx.x & 7;          // which float4 of the row
    const int row_in_b = threadIdx.x >> 3;         // row slot within block-iter
    const int base_row = blockIdx.x * (ROWS_PER_ITER * ITERS);

    const float4* __restrict__ o4 = reinterpret_cast<const float4*>(outputs);
    const float4* __restrict__ t4 = reinterpret_cast<const float4*>(targets);

    const int idx0 = (base_row + row_in_b) * (D_DIM / 4) + sub;

    // ---- front-batched loads: 8 independent LDG.128 in flight ----
    float4 a0 = o4[idx0 + 0 * F4_PER_ITER];
    float4 a1 = o4[idx0 + 1 * F4_PER_ITER];
    float4 a2 = o4[idx0 + 2 * F4_PER_ITER];
    float4 a3 = o4[idx0 + 3 * F4_PER_ITER];
    float4 b0 = t4[idx0 + 0 * F4_PER_ITER];
    float4 b1 = t4[idx0 + 1 * F4_PER_ITER];
    float4 b2 = t4[idx0 + 2 * F4_PER_ITER];
    float4 b3 = t4[idx0 + 3 * F4_PER_ITER];

    float dx, dy, dz, dw;
    #define SSQ(a, b) (dx = a.x - b.x, dy = a.y - b.y, dz = a.z - b.z, \
                       dw = a.w - b.w, dx*dx + dy*dy + dz*dz + dw*dw)
    float s0 = SSQ(a0, b0);
    float s1 = SSQ(a1, b1);
    float s2 = SSQ(a2, b2);
    float s3 = SSQ(a3, b3);
    #undef SSQ

    // Reduce the 8 lanes covering each row (4 independent chains)
    s0 += __shfl_xor_sync(0xFFFFFFFFu, s0, 1);
    s1 += __shfl_xor_sync(0xFFFFFFFFu, s1, 1);
    s2 += __shfl_xor_sync(0xFFFFFFFFu, s2, 1);
    s3 += __shfl_xor_sync(0xFFFFFFFFu, s3, 1);
    s0 += __shfl_xor_sync(0xFFFFFFFFu, s0, 2);
    s1 += __shfl_xor_sync(0xFFFFFFFFu, s1, 2);
    s2 += __shfl_xor_sync(0xFFFFFFFFu, s2, 2);
    s3 += __shfl_xor_sync(0xFFFFFFFFu, s3, 2);
    s0 += __shfl_xor_sync(0xFFFFFFFFu, s0, 4);
    s1 += __shfl_xor_sync(0xFFFFFFFFu, s1, 4);
    s2 += __shfl_xor_sync(0xFFFFFFFFu, s2, 4);
    s3 += __shfl_xor_sync(0xFFFFFFFFu, s3, 4);

    float acc = 0.0f;
    if (sub == 0)
        acc = sqrtf(s0) + sqrtf(s1) + sqrtf(s2) + sqrtf(s3);

    // Combine the 4 row-accumulators per warp (lanes 0,8,16,24 nonzero)
    acc += __shfl_xor_sync(0xFFFFFFFFu, acc, 8);
    acc += __shfl_xor_sync(0xFFFFFFFFu, acc, 16);

    __shared__ float wsum[THREADS / 32];
    if ((threadIdx.x & 31) == 0)
        wsum[threadIdx.x >> 5] = acc;
    __syncthreads();

    __shared__ bool s_is_last;
    if (threadIdx.x == 0) {
        float bsum = 0.0f;
        #pragma unroll
        for (int i = 0; i < THREADS / 32; i++)
            bsum += wsum[i];
        g_partials[blockIdx.x] = bsum;
        __threadfence();
        unsigned int prev = atomicAdd(&g_done_count, 1u);
        s_is_last = (prev == NBLOCKS - 1);
    }
    __syncthreads();

    if (s_is_last) {
        // Final reduce over NBLOCKS partials via float4, fixed order.
        const float4* __restrict__ p4 =
            reinterpret_cast<const float4*>(g_partials);
        float s = 0.0f;
        #pragma unroll
        for (int i = threadIdx.x; i < NBLOCKS / 4; i += THREADS) {
            float4 v = p4[i];
            s += (v.x + v.y) + (v.z + v.w);
        }

        s += __shfl_xor_sync(0xFFFFFFFFu, s, 1);
        s += __shfl_xor_sync(0xFFFFFFFFu, s, 2);
        s += __shfl_xor_sync(0xFFFFFFFFu, s, 4);
        s += __shfl_xor_sync(0xFFFFFFFFu, s, 8);
        s += __shfl_xor_sync(0xFFFFFFFFu, s, 16);

        __shared__ float fsum[THREADS / 32];
        if ((threadIdx.x & 31) == 0)
            fsum[threadIdx.x >> 5] = s;
        __syncthreads();

        if (threadIdx.x == 0) {
            float tot = 0.0f;
            #pragma unroll
            for (int i = 0; i < THREADS / 32; i++)
                tot += fsum[i];
            out[0] = tot * (1.0f / (float)B_ROWS);
            g_done_count = 0;   // reset for next graph replay
        }
    }
}

extern "C" void kernel_launch(void* const* d_in, const int* in_sizes, int n_in,
                              void* d_out, int out_size) {
    const float* outputs = (const float*)d_in[0];
    const float* targets = (const float*)d_in[1];
    // d_in[2] (christoffel_symbols) is mathematically dead: vel starts at 0.
    float* out = (float*)d_out;

    geodesic_loss_fused_kernel<<<NBLOCKS, THREADS>>>(outputs, targets, out);
}

// round 15
// speedup vs baseline: 1.1633x; 1.0459x over previous
#include <cuda_runtime.h>
#include <math.h>

// GeodesicLoss: reference initializes velocity to zero, so the geodesic ODE
// acc = -Gamma v v is identically zero for all 10 steps -> traj == outputs.
// Result is exactly mean_b || outputs_b - targets_b ||_2.
// Pure streaming reduction over 128 MiB -> DRAM-bound.
//
// R15: identical to R14 except __launch_bounds__(256, 2): register budget
// 128/thread so ptxas keeps ALL 8 front-batched LDG.128 results live
// (R14's budget of 64 yielded regs=40 / MLP ~4-5, DRAM 70.1%). 16 warps/SM
// x MLP 8 = 128 in-flight loads/SM -- occupancy is not the binding
// constraint, load-in-flight supply is.

#define B_ROWS   524288
#define D_DIM    32
#define THREADS  256
#define NBLOCKS  4096
#define ROWS_PER_ITER (THREADS / 8)                         // 32 rows / block-iter
#define ITERS 4                                             // 128 rows / block
#define F4_PER_ITER (ROWS_PER_ITER * (D_DIM / 4))           // 256 float4 stride

__device__ float        g_partials[NBLOCKS];
__device__ unsigned int g_done_count = 0;

__global__ __launch_bounds__(THREADS, 2)
void geodesic_loss_fused_kernel(const float* __restrict__ outputs,
                                const float* __restrict__ targets,
                                float* __restrict__ out) {
    const int sub      = threadIdx.x & 7;          // which float4 of the row
    const int row_in_b = threadIdx.x >> 3;         // row slot within block-iter
    const int base_row = blockIdx.x * (ROWS_PER_ITER * ITERS);

    const float4* __restrict__ o4 = reinterpret_cast<const float4*>(outputs);
    const float4* __restrict__ t4 = reinterpret_cast<const float4*>(targets);

    const int idx0 = (base_row + row_in_b) * (D_DIM / 4) + sub;

    // ---- front-batched loads: 8 independent LDG.128 in flight ----
    float4 a0 = o4[idx0 + 0 * F4_PER_ITER];
    float4 a1 = o4[idx0 + 1 * F4_PER_ITER];
    float4 a2 = o4[idx0 + 2 * F4_PER_ITER];
    float4 a3 = o4[idx0 + 3 * F4_PER_ITER];
    float4 b0 = t4[idx0 + 0 * F4_PER_ITER];
    float4 b1 = t4[idx0 + 1 * F4_PER_ITER];
    float4 b2 = t4[idx0 + 2 * F4_PER_ITER];
    float4 b3 = t4[idx0 + 3 * F4_PER_ITER];

    float dx, dy, dz, dw;
    #define SSQ(a, b) (dx = a.x - b.x, dy = a.y - b.y, dz = a.z - b.z, \
                       dw = a.w - b.w, dx*dx + dy*dy + dz*dz + dw*dw)
    float s0 = SSQ(a0, b0);
    float s1 = SSQ(a1, b1);
    float s2 = SSQ(a2, b2);
    float s3 = SSQ(a3, b3);
    #undef SSQ

    // Reduce the 8 lanes covering each row (4 independent chains)
    s0 += __shfl_xor_sync(0xFFFFFFFFu, s0, 1);
    s1 += __shfl_xor_sync(0xFFFFFFFFu, s1, 1);
    s2 += __shfl_xor_sync(0xFFFFFFFFu, s2, 1);
    s3 += __shfl_xor_sync(0xFFFFFFFFu, s3, 1);
    s0 += __shfl_xor_sync(0xFFFFFFFFu, s0, 2);
    s1 += __shfl_xor_sync(0xFFFFFFFFu, s1, 2);
    s2 += __shfl_xor_sync(0xFFFFFFFFu, s2, 2);
    s3 += __shfl_xor_sync(0xFFFFFFFFu, s3, 2);
    s0 += __shfl_xor_sync(0xFFFFFFFFu, s0, 4);
    s1 += __shfl_xor_sync(0xFFFFFFFFu, s1, 4);
    s2 += __shfl_xor_sync(0xFFFFFFFFu, s2, 4);
    s3 += __shfl_xor_sync(0xFFFFFFFFu, s3, 4);

    float acc = 0.0f;
    if (sub == 0)
        acc = sqrtf(s0) + sqrtf(s1) + sqrtf(s2) + sqrtf(s3);

    // Combine the 4 row-accumulators per warp (lanes 0,8,16,24 nonzero)
    acc += __shfl_xor_sync(0xFFFFFFFFu, acc, 8);
    acc += __shfl_xor_sync(0xFFFFFFFFu, acc, 16);

    __shared__ float wsum[THREADS / 32];
    if ((threadIdx.x & 31) == 0)
        wsum[threadIdx.x >> 5] = acc;
    __syncthreads();

    __shared__ bool s_is_last;
    if (threadIdx.x == 0) {
        float bsum = 0.0f;
        #pragma unroll
        for (int i = 0; i < THREADS / 32; i++)
            bsum += wsum[i];
        g_partials[blockIdx.x] = bsum;
        __threadfence();
        unsigned int prev = atomicAdd(&g_done_count, 1u);
        s_is_last = (prev == NBLOCKS - 1);
    }
    __syncthreads();

    if (s_is_last) {
        // Final reduce over NBLOCKS partials via float4, fixed order.
        const float4* __restrict__ p4 =
            reinterpret_cast<const float4*>(g_partials);
        float s = 0.0f;
        #pragma unroll
        for (int i = threadIdx.x; i < NBLOCKS / 4; i += THREADS) {
            float4 v = p4[i];
            s += (v.x + v.y) + (v.z + v.w);
        }

        s += __shfl_xor_sync(0xFFFFFFFFu, s, 1);
        s += __shfl_xor_sync(0xFFFFFFFFu, s, 2);
        s += __shfl_xor_sync(0xFFFFFFFFu, s, 4);
        s += __shfl_xor_sync(0xFFFFFFFFu, s, 8);
        s += __shfl_xor_sync(0xFFFFFFFFu, s, 16);

        __shared__ float fsum[THREADS / 32];
        if ((threadIdx.x & 31) == 0)
            fsum[threadIdx.x >> 5] = s;
        __syncthreads();

        if (threadIdx.x == 0) {
            float tot = 0.0f;
            #pragma unroll
            for (int i = 0; i < THREADS / 32; i++)
                tot += fsum[i];
            out[0] = tot * (1.0f / (float)B_ROWS);
            g_done_count = 0;   // reset for next graph replay
        }
    }
}

extern "C" void kernel_launch(void* const* d_in, const int* in_sizes, int n_in,
                              void* d_out, int out_size) {
    const float* outputs = (const float*)d_in[0];
    const float* targets = (const float*)d_in[1];
    // d_in[2] (christoffel_symbols) is mathematically dead: vel starts at 0.
    float* out = (float*)d_out;

    geodesic_loss_fused_kernel<<<NBLOCKS, THREADS>>>(outputs, targets, out);
}